// round 12
// baseline (speedup 1.0000x reference)
#include <cuda_runtime.h>
#include <cuda_bf16.h>
#include <cstdint>
#include <math.h>

// Problem constants
#define BATCH   64
#define SEQ     197
#define HIDDEN  768
#define HEADS   12
#define HDIM    64
#define KRANK   64
#define MROWS   (BATCH * SEQ)          // 12608
#define HH      (HIDDEN * HIDDEN)
#define KPAD    224                    // SEQ padded to 7*32

// ---------------------------------------------------------------------------
// Scratch (no allocations allowed): device globals
// ---------------------------------------------------------------------------
__device__ float g_Q  [MROWS * HIDDEN];
__device__ float g_K  [MROWS * HIDDEN];
__device__ float g_V  [MROWS * HIDDEN];
__device__ float g_CTX[MROWS * HIDDEN];
__device__ float g_PK [BATCH * KRANK * HIDDEN];
__device__ float g_PV [BATCH * KRANK * HIDDEN];
__device__ float g_Wt [4 * HH];            // transposed + rounded + col-permuted weights
__device__ float g_Et [2 * KRANK * KPAD];  // E^T, tf32-rounded, zero-padded

// ---------------------------------------------------------------------------
// Helpers
// ---------------------------------------------------------------------------
static __device__ __forceinline__ uint32_t smem_u32(const void* p) {
    uint32_t a;
    asm("{ .reg .u64 t; cvta.to.shared.u64 t, %1; cvt.u32.u64 %0, t; }"
        : "=r"(a) : "l"(p));
    return a;
}
static __device__ __forceinline__ void cpa16(uint32_t s, const void* g) {
    asm volatile("cp.async.cg.shared.global [%0], [%1], 16;" :: "r"(s), "l"(g));
}
static __device__ __forceinline__ float rna_tf32(float x) {
    uint32_t u;
    asm("cvt.rna.tf32.f32 %0, %1;" : "=r"(u) : "f"(x));
    return __uint_as_float(u);
}
static __device__ __forceinline__ uint32_t rna_u(float x) {
    uint32_t u;
    asm("cvt.rna.tf32.f32 %0, %1;" : "=r"(u) : "f"(x));
    return u;
}
static __device__ __forceinline__ void mma_tf32(
    float* c, const uint32_t* a, uint32_t b0, uint32_t b1)
{
    asm volatile(
        "mma.sync.aligned.m16n8k8.row.col.f32.tf32.tf32.f32 "
        "{%0,%1,%2,%3}, {%4,%5,%6,%7}, {%8,%9}, {%0,%1,%2,%3};"
        : "+f"(c[0]), "+f"(c[1]), "+f"(c[2]), "+f"(c[3])
        : "r"(a[0]), "r"(a[1]), "r"(a[2]), "r"(a[3]), "r"(b0), "r"(b1));
}

struct GSet { const float* Bt; const float* bias; float* C; };

// ---------------------------------------------------------------------------
// tf32 HMMA GEMM: C[M,768] = A[M,768] @ W + bias
//   W transposed [n][k], tf32-rounded, k-cols permuted per 32-block:
//   p(c) = (c&3)*8 + (c>>2)  -> per-thread B fragments become float4 loads.
//   A raw fp32, rounded per-fragment in registers.
// CTA tile 128x256, 8 warps (2 m-rows x 4 n-cols, warp tile 64x64),
// K-chunk 32, 3-stage cp.async, one __syncthreads per chunk.
// Arithmetic intensity: 1M MACs vs 176KB smem traffic per chunk ->
// tensor pipe (2048 cyc) binds, smem crossbar (1408 cyc) has headroom.
// ---------------------------------------------------------------------------
#define LDP 36
#define CTAN 256
#define STAGE_F ((128 + CTAN) * LDP)       // 13824 floats
#define GEMM_SMEM (3 * STAGE_F * 4)        // 165888 bytes

__global__ __launch_bounds__(256, 1) void gemm_tf32(
    const float* __restrict__ A, GSet s0, GSet s1, GSet s2)
{
    extern __shared__ float sm[];
    const GSet g = (blockIdx.z == 0) ? s0 : (blockIdx.z == 1) ? s1 : s2;
    const float* __restrict__ Bt   = g.Bt;
    const float* __restrict__ bias = g.bias;
    float* __restrict__ C          = g.C;

    const int tid  = threadIdx.x;
    const int wid  = tid >> 5;
    const int lane = tid & 31;
    const int gid  = lane >> 2;
    const int tg   = lane & 3;
    const int wm   = (wid >> 2) * 64;      // 0 or 64
    const int wn   = (wid & 3) * 64;       // 0,64,128,192
    const int row0 = blockIdx.y * 128;
    const int col0 = blockIdx.x * CTAN;

    const int lrow = tid >> 3;             // 0..31
    const int lseg = tid & 7;              // 0..7

    float acc[4][8][4];
    #pragma unroll
    for (int i = 0; i < 4; ++i)
        #pragma unroll
        for (int j = 0; j < 8; ++j)
            #pragma unroll
            for (int r = 0; r < 4; ++r) acc[i][j][r] = 0.f;

#define LOAD_STAGE(s, t) do {                                                  \
    const int _k0 = (t) * 32;                                                  \
    float* _dA = sm + (s) * STAGE_F;                                           \
    float* _dB = _dA + 128 * LDP;                                              \
    _Pragma("unroll")                                                          \
    for (int _i = 0; _i < 4; ++_i) {                                           \
        int _row = lrow + _i * 32;                                             \
        int _ar = row0 + _row; if (_ar > MROWS - 1) _ar = MROWS - 1;           \
        cpa16(smem_u32(_dA + _row * LDP + lseg * 4),                           \
              A + (long)_ar * HIDDEN + _k0 + lseg * 4);                        \
    }                                                                          \
    _Pragma("unroll")                                                          \
    for (int _i = 0; _i < 8; ++_i) {                                           \
        int _row = (_i * 256 + tid) >> 3;                                      \
        cpa16(smem_u32(_dB + _row * LDP + lseg * 4),                           \
              Bt + (long)(col0 + _row) * HIDDEN + _k0 + lseg * 4);             \
    }                                                                          \
    asm volatile("cp.async.commit_group;" ::: "memory");                       \
} while (0)

    LOAD_STAGE(0, 0);
    LOAD_STAGE(1, 1);

    for (int t = 0; t < 24; ++t) {
        if (t < 23) asm volatile("cp.async.wait_group 1;" ::: "memory");
        else        asm volatile("cp.async.wait_group 0;" ::: "memory");
        __syncthreads();              // prev-chunk compute done + data visible

        if (t < 22) LOAD_STAGE((t + 2) % 3, t + 2);

        const float* As = sm + (t % 3) * STAGE_F;
        const float* Bs = As + 128 * LDP;

        uint32_t a[4][4];
        float4 bv[8];

        #pragma unroll
        for (int k8 = 0; k8 < 4; ++k8) {
            const int kb = k8 * 8;
            if ((k8 & 1) == 0) {
                // permuted layout: one float4 covers this k8-pair's B frags
                #pragma unroll
                for (int nj = 0; nj < 8; ++nj) {
                    const int n = wn + nj * 8 + gid;
                    bv[nj] = *(const float4*)&Bs[n * LDP + tg * 8 + (k8 >> 1) * 4];
                }
            }
            #pragma unroll
            for (int mi = 0; mi < 4; ++mi) {
                const int r = wm + mi * 16 + gid;
                a[mi][0] = rna_u(As[r       * LDP + kb + tg]);
                a[mi][1] = rna_u(As[(r + 8) * LDP + kb + tg]);
                a[mi][2] = rna_u(As[r       * LDP + kb + tg + 4]);
                a[mi][3] = rna_u(As[(r + 8) * LDP + kb + tg + 4]);
            }
            #pragma unroll
            for (int mi = 0; mi < 4; ++mi)
                #pragma unroll
                for (int nj = 0; nj < 8; ++nj) {
                    const uint32_t b0 = (k8 & 1) ? __float_as_uint(bv[nj].z)
                                                 : __float_as_uint(bv[nj].x);
                    const uint32_t b1 = (k8 & 1) ? __float_as_uint(bv[nj].w)
                                                 : __float_as_uint(bv[nj].y);
                    mma_tf32(acc[mi][nj], a[mi], b0, b1);
                }
        }
    }
#undef LOAD_STAGE

    // epilogue
    #pragma unroll
    for (int nj = 0; nj < 8; ++nj) {
        const int cb = col0 + wn + nj * 8 + tg * 2;
        const float bx = bias[cb];
        const float by = bias[cb + 1];
        #pragma unroll
        for (int mi = 0; mi < 4; ++mi) {
            const int r = row0 + wm + mi * 16 + gid;
            if (r < MROWS) {
                float2 v = make_float2(acc[mi][nj][0] + bx, acc[mi][nj][1] + by);
                *(float2*)(C + (long)r * HIDDEN + cb) = v;
            }
            if (r + 8 < MROWS) {
                float2 v = make_float2(acc[mi][nj][2] + bx, acc[mi][nj][3] + by);
                *(float2*)(C + (long)(r + 8) * HIDDEN + cb) = v;
            }
        }
    }
}

// ---------------------------------------------------------------------------
// Low-rank projection on tensor cores:
//   OUT[b][k][c] = sum_s Et[k][s] * SRC[b*SEQ+s][c],  K-dim padded to 224
// CTA tile 64x128, 8 warps (2x4, warp tile 32x32), grid (6, BATCH, 2).
// ---------------------------------------------------------------------------
#define PLDB 132
#define PSTAGE_F (64 * LDP + 32 * PLDB)     // 6528 floats
#define PROJ_SMEM (3 * PSTAGE_F * 4)        // 78336 bytes

__global__ __launch_bounds__(256, 2) void proj_mma(
    const float* __restrict__ Et2,   // [2][KRANK][KPAD]
    const float* __restrict__ K_,
    const float* __restrict__ V_,
    float* __restrict__ PK_, float* __restrict__ PV_)
{
    extern __shared__ float sm[];
    const int zsel = blockIdx.z;
    const float* __restrict__ Et  = Et2 + (long)zsel * KRANK * KPAD;
    const float* __restrict__ SRC = zsel ? V_ : K_;
    float* __restrict__ OUT       = zsel ? PV_ : PK_;

    const int tid  = threadIdx.x;
    const int wid  = tid >> 5;
    const int lane = tid & 31;
    const int gid  = lane >> 2;
    const int tg   = lane & 3;
    const int wm   = (wid >> 2) * 32;
    const int wn   = (wid & 3) * 32;
    const int col0 = blockIdx.x * 128;
    const int b    = blockIdx.y;

    float acc[2][4][4];
    #pragma unroll
    for (int i = 0; i < 2; ++i)
        #pragma unroll
        for (int j = 0; j < 4; ++j)
            #pragma unroll
            for (int r = 0; r < 4; ++r) acc[i][j][r] = 0.f;

#define PLOAD_STAGE(s, t) do {                                                 \
    const int _k0 = (t) * 32;                                                  \
    float* _dA = sm + (s) * PSTAGE_F;                                          \
    float* _dB = _dA + 64 * LDP;                                               \
    _Pragma("unroll")                                                          \
    for (int _i = 0; _i < 2; ++_i) {                                           \
        int _idx = _i * 256 + tid;                                             \
        int _row = _idx >> 3, _seg = _idx & 7;                                 \
        cpa16(smem_u32(_dA + _row * LDP + _seg * 4),                           \
              Et + (long)_row * KPAD + _k0 + _seg * 4);                        \
    }                                                                          \
    _Pragma("unroll")                                                          \
    for (int _i = 0; _i < 4; ++_i) {                                           \
        int _idx = _i * 256 + tid;                                             \
        int _row = _idx >> 5, _seg = _idx & 31;                                \
        int _s = _k0 + _row; if (_s > SEQ - 1) _s = SEQ - 1;                   \
        cpa16(smem_u32(_dB + _row * PLDB + _seg * 4),                          \
              SRC + ((long)b * SEQ + _s) * HIDDEN + col0 + _seg * 4);          \
    }                                                                          \
    asm volatile("cp.async.commit_group;" ::: "memory");                       \
} while (0)

    PLOAD_STAGE(0, 0);
    PLOAD_STAGE(1, 1);

    for (int t = 0; t < 7; ++t) {
        if (t < 6) asm volatile("cp.async.wait_group 1;" ::: "memory");
        else       asm volatile("cp.async.wait_group 0;" ::: "memory");
        __syncthreads();

        if (t < 5) PLOAD_STAGE((t + 2) % 3, t + 2);

        const float* As = sm + (t % 3) * PSTAGE_F;
        const float* Bs = As + 64 * LDP;

        #pragma unroll
        for (int k8 = 0; k8 < 4; ++k8) {
            const int kb = k8 * 8;
            uint32_t a[2][4], bb[4][2];
            #pragma unroll
            for (int mi = 0; mi < 2; ++mi) {
                const int r = wm + mi * 16 + gid;
                a[mi][0] = __float_as_uint(As[r       * LDP + kb + tg]);
                a[mi][1] = __float_as_uint(As[(r + 8) * LDP + kb + tg]);
                a[mi][2] = __float_as_uint(As[r       * LDP + kb + tg + 4]);
                a[mi][3] = __float_as_uint(As[(r + 8) * LDP + kb + tg + 4]);
            }
            #pragma unroll
            for (int nj = 0; nj < 4; ++nj) {
                const int n = wn + nj * 8 + gid;
                bb[nj][0] = rna_u(Bs[(kb + tg)     * PLDB + n]);
                bb[nj][1] = rna_u(Bs[(kb + tg + 4) * PLDB + n]);
            }
            #pragma unroll
            for (int mi = 0; mi < 2; ++mi)
                #pragma unroll
                for (int nj = 0; nj < 4; ++nj)
                    mma_tf32(acc[mi][nj], a[mi], bb[nj][0], bb[nj][1]);
        }
    }
#undef PLOAD_STAGE

    #pragma unroll
    for (int nj = 0; nj < 4; ++nj) {
        const int cb = col0 + wn + nj * 8 + tg * 2;
        #pragma unroll
        for (int mi = 0; mi < 2; ++mi) {
            const int r = wm + mi * 16 + gid;
            float2 v0 = make_float2(acc[mi][nj][0], acc[mi][nj][1]);
            float2 v1 = make_float2(acc[mi][nj][2], acc[mi][nj][3]);
            *(float2*)(OUT + ((long)b * KRANK + r)     * HIDDEN + cb) = v0;
            *(float2*)(OUT + ((long)b * KRANK + r + 8) * HIDDEN + cb) = v1;
        }
    }
}

// ---------------------------------------------------------------------------
// Weight transpose + tf32 round + per-32-block column permutation:
//   T[n][kblk + p(klocal)] = rna(W[k][n]),  p(c) = (c&3)*8 + (c>>2)
// ---------------------------------------------------------------------------
__global__ __launch_bounds__(256) void wtrans_round4(
    const float* __restrict__ W0, const float* __restrict__ W1,
    const float* __restrict__ W2, const float* __restrict__ W3,
    float* __restrict__ Tbase)
{
    const float* W = (blockIdx.z == 0) ? W0 : (blockIdx.z == 1) ? W1
                   : (blockIdx.z == 2) ? W2 : W3;
    float* T = Tbase + (long)blockIdx.z * HH;

    __shared__ float t[32][33];
    const int bx = blockIdx.x * 32;   // n
    const int by = blockIdx.y * 32;   // k block (32-aligned)
    const int x = threadIdx.x & 31, y = threadIdx.x >> 5;
    #pragma unroll
    for (int i = 0; i < 32; i += 8)
        t[y + i][x] = W[(by + y + i) * HIDDEN + bx + x];
    __syncthreads();
    const int p = (x & 3) * 8 + (x >> 2);   // permuted k position within block
    #pragma unroll
    for (int i = 0; i < 32; i += 8)
        T[(bx + y + i) * HIDDEN + by + p] = rna_tf32(t[x][y + i]);
}

// ---------------------------------------------------------------------------
// E^T prep: Et[z][m][s] = rna(E_z[s][m]) for s<197 else 0
// ---------------------------------------------------------------------------
__global__ __launch_bounds__(256) void et_prep(
    const float* __restrict__ Ek, const float* __restrict__ Ev,
    float* __restrict__ Et2)
{
    int idx = blockIdx.x * 256 + threadIdx.x;
    if (idx >= 2 * KRANK * KPAD) return;
    int z = idx / (KRANK * KPAD);
    int r = idx % (KRANK * KPAD);
    int m = r / KPAD, s = r % KPAD;
    const float* E = z ? Ev : Ek;
    Et2[idx] = (s < SEQ) ? rna_tf32(E[s * KRANK + m]) : 0.f;
}

// ---------------------------------------------------------------------------
// Fused low-rank attention per (b,h) (fp32)
// ---------------------------------------------------------------------------
__global__ __launch_bounds__(128) void lowrank_attn(
    const float* __restrict__ Q, const float* __restrict__ PK,
    const float* __restrict__ PV, float* __restrict__ CTX)
{
    const int h = blockIdx.x;
    const int b = blockIdx.y;

    __shared__ float pk_s[64 * 65];
    __shared__ float pv_s[64 * 64];
    __shared__ float qs[4][64];
    __shared__ float ps[4][64];

    const int tid  = threadIdx.x;
    const int w    = tid >> 5;
    const int lane = tid & 31;

    const float* pkg = PK + ((long)b * KRANK) * HIDDEN + h * HDIM;
    const float* pvg = PV + ((long)b * KRANK) * HIDDEN + h * HDIM;
    for (int i = tid; i < 64 * 64; i += 128) {
        int k = i >> 6, d = i & 63;
        pk_s[k * 65 + d] = pkg[(long)k * HIDDEN + d];
        pv_s[k * 64 + d] = pvg[(long)k * HIDDEN + d];
    }
    __syncthreads();

    const float scale = 0.125f;

    for (int s = w; s < SEQ; s += 4) {
        const float* qg = Q + ((long)b * SEQ + s) * HIDDEN + h * HDIM;
        qs[w][lane]      = qg[lane];
        qs[w][lane + 32] = qg[lane + 32];
        __syncwarp();

        float s0 = 0.f, s1 = 0.f;
        const float* p0 = &pk_s[lane * 65];
        const float* p1 = &pk_s[(lane + 32) * 65];
        #pragma unroll
        for (int d = 0; d < 64; ++d) {
            float qd = qs[w][d];
            s0 = fmaf(qd, p0[d], s0);
            s1 = fmaf(qd, p1[d], s1);
        }
        s0 *= scale; s1 *= scale;

        float mx = fmaxf(s0, s1);
        #pragma unroll
        for (int o = 16; o > 0; o >>= 1)
            mx = fmaxf(mx, __shfl_xor_sync(0xffffffffu, mx, o));
        float e0 = expf(s0 - mx);
        float e1 = expf(s1 - mx);
        float sm = e0 + e1;
        #pragma unroll
        for (int o = 16; o > 0; o >>= 1)
            sm += __shfl_xor_sync(0xffffffffu, sm, o);
        float inv = 1.f / sm;
        ps[w][lane]      = e0 * inv;
        ps[w][lane + 32] = e1 * inv;
        __syncwarp();

        float c0 = 0.f, c1 = 0.f;
        #pragma unroll
        for (int k = 0; k < 64; ++k) {
            float p = ps[w][k];
            c0 = fmaf(p, pv_s[k * 64 + lane],      c0);
            c1 = fmaf(p, pv_s[k * 64 + lane + 32], c1);
        }
        float* cg = CTX + ((long)b * SEQ + s) * HIDDEN + h * HDIM;
        cg[lane]      = c0;
        cg[lane + 32] = c1;
        __syncwarp();
    }
}

// ---------------------------------------------------------------------------
// Launch orchestration
// ---------------------------------------------------------------------------
extern "C" void kernel_launch(void* const* d_in, const int* in_sizes, int n_in,
                              void* d_out, int out_size)
{
    const float* hs = (const float*)d_in[0];
    const float* Wq = (const float*)d_in[1];
    const float* bq = (const float*)d_in[2];
    const float* Wk = (const float*)d_in[3];
    const float* bk = (const float*)d_in[4];
    const float* Wv = (const float*)d_in[5];
    const float* bv = (const float*)d_in[6];
    const float* Wo = (const float*)d_in[7];
    const float* bo = (const float*)d_in[8];
    const float* Ek = (const float*)d_in[9];
    const float* Ev = (const float*)d_in[10];
    float* out = (float*)d_out;

    float *pQ, *pK, *pV, *pCTX, *pPK, *pPV, *pWt, *pEt;
    cudaGetSymbolAddress((void**)&pQ,   g_Q);
    cudaGetSymbolAddress((void**)&pK,   g_K);
    cudaGetSymbolAddress((void**)&pV,   g_V);
    cudaGetSymbolAddress((void**)&pCTX, g_CTX);
    cudaGetSymbolAddress((void**)&pPK,  g_PK);
    cudaGetSymbolAddress((void**)&pPV,  g_PV);
    cudaGetSymbolAddress((void**)&pWt,  g_Wt);
    cudaGetSymbolAddress((void**)&pEt,  g_Et);

    cudaFuncSetAttribute(gemm_tf32, cudaFuncAttributeMaxDynamicSharedMemorySize,
                         GEMM_SMEM);
    cudaFuncSetAttribute(proj_mma, cudaFuncAttributeMaxDynamicSharedMemorySize,
                         PROJ_SMEM);

    // prep
    dim3 tgrid(HIDDEN / 32, HIDDEN / 32, 4);          // (24,24,4)
    wtrans_round4<<<tgrid, 256>>>(Wq, Wk, Wv, Wo, pWt);
    const int etN = 2 * KRANK * KPAD;
    et_prep<<<(etN + 255) / 256, 256>>>(Ek, Ev, pEt);

    // fused QKV projections
    GSet sq = { pWt + 0 * HH, bq, pQ };
    GSet sk = { pWt + 1 * HH, bk, pK };
    GSet sv = { pWt + 2 * HH, bv, pV };
    dim3 ggrid3(HIDDEN / CTAN, (MROWS + 127) / 128, 3);   // (3, 99, 3)
    gemm_tf32<<<ggrid3, 256, GEMM_SMEM>>>(hs, sq, sk, sv);

    // low-rank projections
    dim3 pgrid(HIDDEN / 128, BATCH, 2);                   // (6, 64, 2)
    proj_mma<<<pgrid, 256, PROJ_SMEM>>>(pEt, pK, pV, pPK, pPV);

    // attention
    dim3 attnGrid(HEADS, BATCH);
    lowrank_attn<<<attnGrid, 128>>>(pQ, pPK, pPV, pCTX);

    // output projection
    GSet so = { pWt + 3 * HH, bo, out };
    dim3 ggrid1(HIDDEN / CTAN, (MROWS + 127) / 128, 1);   // (3, 99, 1)
    gemm_tf32<<<ggrid1, 256, GEMM_SMEM>>>(pCTX, so, so, so);
}

// round 13
// speedup vs baseline: 1.1984x; 1.1984x over previous
#include <cuda_runtime.h>
#include <cuda_bf16.h>
#include <cstdint>
#include <math.h>

// Problem constants
#define BATCH   64
#define SEQ     197
#define HIDDEN  768
#define HEADS   12
#define HDIM    64
#define KRANK   64
#define MROWS   (BATCH * SEQ)          // 12608
#define HH      (HIDDEN * HIDDEN)
#define KPAD    224                    // SEQ padded to 7*32
#define KHALF   (HIDDEN / 2)           // 384 packed uint32 per row

// ---------------------------------------------------------------------------
// Scratch (no allocations allowed): device globals
// ---------------------------------------------------------------------------
__device__ float g_Q  [MROWS * HIDDEN];
__device__ float g_K  [MROWS * HIDDEN];
__device__ float g_V  [MROWS * HIDDEN];
__device__ float g_CTX[MROWS * HIDDEN];
__device__ float g_PK [BATCH * KRANK * HIDDEN];
__device__ float g_PV [BATCH * KRANK * HIDDEN];
__device__ float g_Et [2 * KRANK * KPAD];       // E^T, tf32-rounded, zero-padded
__device__ uint32_t g_AH [MROWS * KHALF];        // activations, bf16-hi packed pairs
__device__ uint32_t g_AL [MROWS * KHALF];        // bf16-lo residual
__device__ uint32_t g_WtH[4 * HIDDEN * KHALF];   // W^T [n][k/2] bf16-hi pairs
__device__ uint32_t g_WtL[4 * HIDDEN * KHALF];   // bf16-lo

// ---------------------------------------------------------------------------
// Helpers
// ---------------------------------------------------------------------------
static __device__ __forceinline__ uint32_t smem_u32(const void* p) {
    uint32_t a;
    asm("{ .reg .u64 t; cvta.to.shared.u64 t, %1; cvt.u32.u64 %0, t; }"
        : "=r"(a) : "l"(p));
    return a;
}
static __device__ __forceinline__ void cpa16(uint32_t s, const void* g) {
    asm volatile("cp.async.cg.shared.global [%0], [%1], 16;" :: "r"(s), "l"(g));
}
static __device__ __forceinline__ float rna_tf32(float x) {
    uint32_t u;
    asm("cvt.rna.tf32.f32 %0, %1;" : "=r"(u) : "f"(x));
    return __uint_as_float(u);
}
static __device__ __forceinline__ uint32_t rna_u(float x) {
    uint32_t u;
    asm("cvt.rna.tf32.f32 %0, %1;" : "=r"(u) : "f"(x));
    return u;
}
static __device__ __forceinline__ void mma_tf32(
    float* c, const uint32_t* a, uint32_t b0, uint32_t b1)
{
    asm volatile(
        "mma.sync.aligned.m16n8k8.row.col.f32.tf32.tf32.f32 "
        "{%0,%1,%2,%3}, {%4,%5,%6,%7}, {%8,%9}, {%0,%1,%2,%3};"
        : "+f"(c[0]), "+f"(c[1]), "+f"(c[2]), "+f"(c[3])
        : "r"(a[0]), "r"(a[1]), "r"(a[2]), "r"(a[3]), "r"(b0), "r"(b1));
}
static __device__ __forceinline__ void mma_bf16(
    float* c, const uint32_t* a, uint32_t b0, uint32_t b1)
{
    asm volatile(
        "mma.sync.aligned.m16n8k16.row.col.f32.bf16.bf16.f32 "
        "{%0,%1,%2,%3}, {%4,%5,%6,%7}, {%8,%9}, {%0,%1,%2,%3};"
        : "+f"(c[0]), "+f"(c[1]), "+f"(c[2]), "+f"(c[3])
        : "r"(a[0]), "r"(a[1]), "r"(a[2]), "r"(a[3]), "r"(b0), "r"(b1));
}
static __device__ __forceinline__ uint32_t pack_bf16(float x, float y) {
    __nv_bfloat162 v = __halves2bfloat162(__float2bfloat16(x), __float2bfloat16(y));
    return *(uint32_t*)&v;
}

struct GSet { const uint32_t* BtH; const uint32_t* BtL; const float* bias; float* C; };

// ---------------------------------------------------------------------------
// Split-bf16 HMMA GEMM: C[M,768] = A[M,768] @ W + bias
//   A given as AH+AL (bf16 pairs packed [row][k/2]); W^T as BtH+BtL [n][k/2].
//   D = AH*BH + AH*BL + AL*BH  (AL*BL ~2^-18, dropped)
// CTA 128x128, 8 warps (2x4, warp tile 64x32), K-chunk 32 (2 k16 steps),
// 3-stage cp.async, one __syncthreads per chunk.
// Smem per stage: 4 regions x 128 rows x 20 uint32 = 40960 B.
// ---------------------------------------------------------------------------
#define LDPU 20
#define REG_U (128 * LDPU)               // 2560 uint32 per region
#define STAGE_U (4 * REG_U)              // 10240 uint32
#define GEMM_SMEM (3 * STAGE_U * 4)      // 122880 bytes

__global__ __launch_bounds__(256, 1) void gemm_bf16s(
    const uint32_t* __restrict__ AH, const uint32_t* __restrict__ AL,
    GSet s0, GSet s1, GSet s2)
{
    extern __shared__ uint32_t smu[];
    const GSet g = (blockIdx.z == 0) ? s0 : (blockIdx.z == 1) ? s1 : s2;
    const uint32_t* __restrict__ BtH = g.BtH;
    const uint32_t* __restrict__ BtL = g.BtL;
    const float* __restrict__ bias   = g.bias;
    float* __restrict__ C            = g.C;

    const int tid  = threadIdx.x;
    const int wid  = tid >> 5;
    const int lane = tid & 31;
    const int gid  = lane >> 2;
    const int tg   = lane & 3;
    const int wm   = (wid >> 2) * 64;
    const int wn   = (wid & 3) * 32;
    const int row0 = blockIdx.y * 128;
    const int col0 = blockIdx.x * 128;

    float acc[4][4][4];
    #pragma unroll
    for (int i = 0; i < 4; ++i)
        #pragma unroll
        for (int j = 0; j < 4; ++j)
            #pragma unroll
            for (int r = 0; r < 4; ++r) acc[i][j][r] = 0.f;

    // per stage: 4 regions (AH, AL, BH, BL), each 128 rows x 16 uint32 (pad 20)
    // thread does 2 rows-segments per region: idx = i*256+tid -> row=idx>>2, seg=idx&3
#define LOAD_STAGE(s, t) do {                                                  \
    const int _k0 = (t) * 16;  /* uint32 offset within packed row */           \
    uint32_t* _st = smu + (s) * STAGE_U;                                       \
    _Pragma("unroll")                                                          \
    for (int _i = 0; _i < 2; ++_i) {                                           \
        int _idx = _i * 256 + tid;                                             \
        int _row = _idx >> 2, _seg = (_idx & 3) * 4;                           \
        int _ar = row0 + _row; if (_ar > MROWS - 1) _ar = MROWS - 1;           \
        long _ao = (long)_ar * KHALF + _k0 + _seg;                             \
        long _bo = (long)(col0 + _row) * KHALF + _k0 + _seg;                   \
        uint32_t _sb = smem_u32(_st + _row * LDPU + _seg);                     \
        cpa16(_sb,                 AH  + _ao);                                 \
        cpa16(_sb + REG_U * 4,     AL  + _ao);                                 \
        cpa16(_sb + 2 * REG_U * 4, BtH + _bo);                                 \
        cpa16(_sb + 3 * REG_U * 4, BtL + _bo);                                 \
    }                                                                          \
    asm volatile("cp.async.commit_group;" ::: "memory");                       \
} while (0)

    LOAD_STAGE(0, 0);
    LOAD_STAGE(1, 1);

    for (int t = 0; t < 24; ++t) {
        if (t < 23) asm volatile("cp.async.wait_group 1;" ::: "memory");
        else        asm volatile("cp.async.wait_group 0;" ::: "memory");
        __syncthreads();              // prev-chunk compute done + data visible

        if (t < 22) LOAD_STAGE((t + 2) % 3, t + 2);

        const uint32_t* Ah = smu + (t % 3) * STAGE_U;
        const uint32_t* Al = Ah + REG_U;
        const uint32_t* Bh = Ah + 2 * REG_U;
        const uint32_t* Bl = Ah + 3 * REG_U;

        #pragma unroll
        for (int k16 = 0; k16 < 2; ++k16) {
            const int kb = k16 * 8;
            uint32_t ah[4][4], al[4][4], bh[4][2], bl[4][2];
            #pragma unroll
            for (int mi = 0; mi < 4; ++mi) {
                const int r = wm + mi * 16 + gid;
                ah[mi][0] = Ah[r       * LDPU + kb + tg];
                ah[mi][1] = Ah[(r + 8) * LDPU + kb + tg];
                ah[mi][2] = Ah[r       * LDPU + kb + tg + 4];
                ah[mi][3] = Ah[(r + 8) * LDPU + kb + tg + 4];
                al[mi][0] = Al[r       * LDPU + kb + tg];
                al[mi][1] = Al[(r + 8) * LDPU + kb + tg];
                al[mi][2] = Al[r       * LDPU + kb + tg + 4];
                al[mi][3] = Al[(r + 8) * LDPU + kb + tg + 4];
            }
            #pragma unroll
            for (int nj = 0; nj < 4; ++nj) {
                const int n = wn + nj * 8 + gid;
                bh[nj][0] = Bh[n * LDPU + kb + tg];
                bh[nj][1] = Bh[n * LDPU + kb + tg + 4];
                bl[nj][0] = Bl[n * LDPU + kb + tg];
                bl[nj][1] = Bl[n * LDPU + kb + tg + 4];
            }
            // product-major ordering: 16 independent accs between reuse
            #pragma unroll
            for (int mi = 0; mi < 4; ++mi)
                #pragma unroll
                for (int nj = 0; nj < 4; ++nj)
                    mma_bf16(acc[mi][nj], ah[mi], bh[nj][0], bh[nj][1]);
            #pragma unroll
            for (int mi = 0; mi < 4; ++mi)
                #pragma unroll
                for (int nj = 0; nj < 4; ++nj)
                    mma_bf16(acc[mi][nj], ah[mi], bl[nj][0], bl[nj][1]);
            #pragma unroll
            for (int mi = 0; mi < 4; ++mi)
                #pragma unroll
                for (int nj = 0; nj < 4; ++nj)
                    mma_bf16(acc[mi][nj], al[mi], bh[nj][0], bh[nj][1]);
        }
    }
#undef LOAD_STAGE

    // epilogue
    #pragma unroll
    for (int nj = 0; nj < 4; ++nj) {
        const int cb = col0 + wn + nj * 8 + tg * 2;
        const float bx = bias[cb];
        const float by = bias[cb + 1];
        #pragma unroll
        for (int mi = 0; mi < 4; ++mi) {
            const int r = row0 + wm + mi * 16 + gid;
            if (r < MROWS) {
                float2 v = make_float2(acc[mi][nj][0] + bx, acc[mi][nj][1] + by);
                *(float2*)(C + (long)r * HIDDEN + cb) = v;
            }
            if (r + 8 < MROWS) {
                float2 v = make_float2(acc[mi][nj][2] + bx, acc[mi][nj][3] + by);
                *(float2*)(C + (long)(r + 8) * HIDDEN + cb) = v;
            }
        }
    }
}

// ---------------------------------------------------------------------------
// fp32 -> packed bf16 hi/lo split (float4 -> 2x uint32 per stream)
// ---------------------------------------------------------------------------
__global__ __launch_bounds__(256) void split_pack(
    const float* __restrict__ X, uint32_t* __restrict__ H,
    uint32_t* __restrict__ L, int n4)
{
    int i = blockIdx.x * 256 + threadIdx.x;
    if (i >= n4) return;
    float4 x = ((const float4*)X)[i];
    float h0 = __bfloat162float(__float2bfloat16(x.x));
    float h1 = __bfloat162float(__float2bfloat16(x.y));
    float h2 = __bfloat162float(__float2bfloat16(x.z));
    float h3 = __bfloat162float(__float2bfloat16(x.w));
    H[2 * i]     = pack_bf16(x.x, x.y);
    H[2 * i + 1] = pack_bf16(x.z, x.w);
    L[2 * i]     = pack_bf16(x.x - h0, x.y - h1);
    L[2 * i + 1] = pack_bf16(x.z - h2, x.w - h3);
}

// ---------------------------------------------------------------------------
// Weight transpose + bf16 hi/lo split: W[k][n] fp32 -> TH/TL[n][k/2] packed
// ---------------------------------------------------------------------------
__global__ __launch_bounds__(256) void wsplit4(
    const float* __restrict__ W0, const float* __restrict__ W1,
    const float* __restrict__ W2, const float* __restrict__ W3,
    uint32_t* __restrict__ THb, uint32_t* __restrict__ TLb)
{
    const float* W = (blockIdx.z == 0) ? W0 : (blockIdx.z == 1) ? W1
                   : (blockIdx.z == 2) ? W2 : W3;
    uint32_t* TH = THb + (long)blockIdx.z * HIDDEN * KHALF;
    uint32_t* TL = TLb + (long)blockIdx.z * HIDDEN * KHALF;

    __shared__ float t[32][33];
    const int bx = blockIdx.x * 32;   // n
    const int by = blockIdx.y * 32;   // k block (32-aligned)
    const int x = threadIdx.x & 31, y = threadIdx.x >> 5;
    #pragma unroll
    for (int i = 0; i < 32; i += 8)
        t[y + i][x] = W[(by + y + i) * HIDDEN + bx + x];
    __syncthreads();
    #pragma unroll
    for (int i = 0; i < 2; ++i) {
        int idx = i * 256 + threadIdx.x;
        int n = idx >> 4, kp = idx & 15;
        float w0 = t[kp * 2][n];
        float w1 = t[kp * 2 + 1][n];
        float h0 = __bfloat162float(__float2bfloat16(w0));
        float h1 = __bfloat162float(__float2bfloat16(w1));
        long o = (long)(bx + n) * KHALF + (by >> 1) + kp;
        TH[o] = pack_bf16(w0, w1);
        TL[o] = pack_bf16(w0 - h0, w1 - h1);
    }
}

// ---------------------------------------------------------------------------
// Low-rank projection on tensor cores (tf32, unchanged from R10):
//   OUT[b][k][c] = sum_s Et[k][s] * SRC[b*SEQ+s][c],  K-dim padded to 224
// ---------------------------------------------------------------------------
#define LDP 36
#define PLDB 132
#define PSTAGE_F (64 * LDP + 32 * PLDB)     // 6528 floats
#define PROJ_SMEM (3 * PSTAGE_F * 4)        // 78336 bytes

__global__ __launch_bounds__(256, 2) void proj_mma(
    const float* __restrict__ Et2,   // [2][KRANK][KPAD]
    const float* __restrict__ K_,
    const float* __restrict__ V_,
    float* __restrict__ PK_, float* __restrict__ PV_)
{
    extern __shared__ float smf[];
    const int zsel = blockIdx.z;
    const float* __restrict__ Et  = Et2 + (long)zsel * KRANK * KPAD;
    const float* __restrict__ SRC = zsel ? V_ : K_;
    float* __restrict__ OUT       = zsel ? PV_ : PK_;

    const int tid  = threadIdx.x;
    const int wid  = tid >> 5;
    const int lane = tid & 31;
    const int gid  = lane >> 2;
    const int tg   = lane & 3;
    const int wm   = (wid >> 2) * 32;
    const int wn   = (wid & 3) * 32;
    const int col0 = blockIdx.x * 128;
    const int b    = blockIdx.y;

    float acc[2][4][4];
    #pragma unroll
    for (int i = 0; i < 2; ++i)
        #pragma unroll
        for (int j = 0; j < 4; ++j)
            #pragma unroll
            for (int r = 0; r < 4; ++r) acc[i][j][r] = 0.f;

#define PLOAD_STAGE(s, t) do {                                                 \
    const int _k0 = (t) * 32;                                                  \
    float* _dA = smf + (s) * PSTAGE_F;                                         \
    float* _dB = _dA + 64 * LDP;                                               \
    _Pragma("unroll")                                                          \
    for (int _i = 0; _i < 2; ++_i) {                                           \
        int _idx = _i * 256 + tid;                                             \
        int _row = _idx >> 3, _seg = _idx & 7;                                 \
        cpa16(smem_u32(_dA + _row * LDP + _seg * 4),                           \
              Et + (long)_row * KPAD + _k0 + _seg * 4);                        \
    }                                                                          \
    _Pragma("unroll")                                                          \
    for (int _i = 0; _i < 4; ++_i) {                                           \
        int _idx = _i * 256 + tid;                                             \
        int _row = _idx >> 5, _seg = _idx & 31;                                \
        int _s = _k0 + _row; if (_s > SEQ - 1) _s = SEQ - 1;                   \
        cpa16(smem_u32(_dB + _row * PLDB + _seg * 4),                          \
              SRC + ((long)b * SEQ + _s) * HIDDEN + col0 + _seg * 4);          \
    }                                                                          \
    asm volatile("cp.async.commit_group;" ::: "memory");                       \
} while (0)

    PLOAD_STAGE(0, 0);
    PLOAD_STAGE(1, 1);

    for (int t = 0; t < 7; ++t) {
        if (t < 6) asm volatile("cp.async.wait_group 1;" ::: "memory");
        else       asm volatile("cp.async.wait_group 0;" ::: "memory");
        __syncthreads();

        if (t < 5) PLOAD_STAGE((t + 2) % 3, t + 2);

        const float* As = smf + (t % 3) * PSTAGE_F;
        const float* Bs = As + 64 * LDP;

        #pragma unroll
        for (int k8 = 0; k8 < 4; ++k8) {
            const int kb = k8 * 8;
            uint32_t a[2][4], bb[4][2];
            #pragma unroll
            for (int mi = 0; mi < 2; ++mi) {
                const int r = wm + mi * 16 + gid;
                a[mi][0] = __float_as_uint(As[r       * LDP + kb + tg]);
                a[mi][1] = __float_as_uint(As[(r + 8) * LDP + kb + tg]);
                a[mi][2] = __float_as_uint(As[r       * LDP + kb + tg + 4]);
                a[mi][3] = __float_as_uint(As[(r + 8) * LDP + kb + tg + 4]);
            }
            #pragma unroll
            for (int nj = 0; nj < 4; ++nj) {
                const int n = wn + nj * 8 + gid;
                bb[nj][0] = rna_u(Bs[(kb + tg)     * PLDB + n]);
                bb[nj][1] = rna_u(Bs[(kb + tg + 4) * PLDB + n]);
            }
            #pragma unroll
            for (int mi = 0; mi < 2; ++mi)
                #pragma unroll
                for (int nj = 0; nj < 4; ++nj)
                    mma_tf32(acc[mi][nj], a[mi], bb[nj][0], bb[nj][1]);
        }
    }
#undef PLOAD_STAGE

    #pragma unroll
    for (int nj = 0; nj < 4; ++nj) {
        const int cb = col0 + wn + nj * 8 + tg * 2;
        #pragma unroll
        for (int mi = 0; mi < 2; ++mi) {
            const int r = wm + mi * 16 + gid;
            float2 v0 = make_float2(acc[mi][nj][0], acc[mi][nj][1]);
            float2 v1 = make_float2(acc[mi][nj][2], acc[mi][nj][3]);
            *(float2*)(OUT + ((long)b * KRANK + r)     * HIDDEN + cb) = v0;
            *(float2*)(OUT + ((long)b * KRANK + r + 8) * HIDDEN + cb) = v1;
        }
    }
}

// ---------------------------------------------------------------------------
// E^T prep: Et[z][m][s] = rna(E_z[s][m]) for s<197 else 0
// ---------------------------------------------------------------------------
__global__ __launch_bounds__(256) void et_prep(
    const float* __restrict__ Ek, const float* __restrict__ Ev,
    float* __restrict__ Et2)
{
    int idx = blockIdx.x * 256 + threadIdx.x;
    if (idx >= 2 * KRANK * KPAD) return;
    int z = idx / (KRANK * KPAD);
    int r = idx % (KRANK * KPAD);
    int m = r / KPAD, s = r % KPAD;
    const float* E = z ? Ev : Ek;
    Et2[idx] = (s < SEQ) ? rna_tf32(E[s * KRANK + m]) : 0.f;
}

// ---------------------------------------------------------------------------
// Fused low-rank attention per (b,h) (fp32, unchanged)
// ---------------------------------------------------------------------------
__global__ __launch_bounds__(128) void lowrank_attn(
    const float* __restrict__ Q, const float* __restrict__ PK,
    const float* __restrict__ PV, float* __restrict__ CTX)
{
    const int h = blockIdx.x;
    const int b = blockIdx.y;

    __shared__ float pk_s[64 * 65];
    __shared__ float pv_s[64 * 64];
    __shared__ float qs[4][64];
    __shared__ float ps[4][64];

    const int tid  = threadIdx.x;
    const int w    = tid >> 5;
    const int lane = tid & 31;

    const float* pkg = PK + ((long)b * KRANK) * HIDDEN + h * HDIM;
    const float* pvg = PV + ((long)b * KRANK) * HIDDEN + h * HDIM;
    for (int i = tid; i < 64 * 64; i += 128) {
        int k = i >> 6, d = i & 63;
        pk_s[k * 65 + d] = pkg[(long)k * HIDDEN + d];
        pv_s[k * 64 + d] = pvg[(long)k * HIDDEN + d];
    }
    __syncthreads();

    const float scale = 0.125f;

    for (int s = w; s < SEQ; s += 4) {
        const float* qg = Q + ((long)b * SEQ + s) * HIDDEN + h * HDIM;
        qs[w][lane]      = qg[lane];
        qs[w][lane + 32] = qg[lane + 32];
        __syncwarp();

        float s0 = 0.f, s1 = 0.f;
        const float* p0 = &pk_s[lane * 65];
        const float* p1 = &pk_s[(lane + 32) * 65];
        #pragma unroll
        for (int d = 0; d < 64; ++d) {
            float qd = qs[w][d];
            s0 = fmaf(qd, p0[d], s0);
            s1 = fmaf(qd, p1[d], s1);
        }
        s0 *= scale; s1 *= scale;

        float mx = fmaxf(s0, s1);
        #pragma unroll
        for (int o = 16; o > 0; o >>= 1)
            mx = fmaxf(mx, __shfl_xor_sync(0xffffffffu, mx, o));
        float e0 = expf(s0 - mx);
        float e1 = expf(s1 - mx);
        float sm = e0 + e1;
        #pragma unroll
        for (int o = 16; o > 0; o >>= 1)
            sm += __shfl_xor_sync(0xffffffffu, sm, o);
        float inv = 1.f / sm;
        ps[w][lane]      = e0 * inv;
        ps[w][lane + 32] = e1 * inv;
        __syncwarp();

        float c0 = 0.f, c1 = 0.f;
        #pragma unroll
        for (int k = 0; k < 64; ++k) {
            float p = ps[w][k];
            c0 = fmaf(p, pv_s[k * 64 + lane],      c0);
            c1 = fmaf(p, pv_s[k * 64 + lane + 32], c1);
        }
        float* cg = CTX + ((long)b * SEQ + s) * HIDDEN + h * HDIM;
        cg[lane]      = c0;
        cg[lane + 32] = c1;
        __syncwarp();
    }
}

// ---------------------------------------------------------------------------
// Launch orchestration
// ---------------------------------------------------------------------------
extern "C" void kernel_launch(void* const* d_in, const int* in_sizes, int n_in,
                              void* d_out, int out_size)
{
    const float* hs = (const float*)d_in[0];
    const float* Wq = (const float*)d_in[1];
    const float* bq = (const float*)d_in[2];
    const float* Wk = (const float*)d_in[3];
    const float* bk = (const float*)d_in[4];
    const float* Wv = (const float*)d_in[5];
    const float* bv = (const float*)d_in[6];
    const float* Wo = (const float*)d_in[7];
    const float* bo = (const float*)d_in[8];
    const float* Ek = (const float*)d_in[9];
    const float* Ev = (const float*)d_in[10];
    float* out = (float*)d_out;

    float *pQ, *pK, *pV, *pCTX, *pPK, *pPV, *pEt;
    uint32_t *pAH, *pAL, *pWH, *pWL;
    cudaGetSymbolAddress((void**)&pQ,   g_Q);
    cudaGetSymbolAddress((void**)&pK,   g_K);
    cudaGetSymbolAddress((void**)&pV,   g_V);
    cudaGetSymbolAddress((void**)&pCTX, g_CTX);
    cudaGetSymbolAddress((void**)&pPK,  g_PK);
    cudaGetSymbolAddress((void**)&pPV,  g_PV);
    cudaGetSymbolAddress((void**)&pEt,  g_Et);
    cudaGetSymbolAddress((void**)&pAH,  g_AH);
    cudaGetSymbolAddress((void**)&pAL,  g_AL);
    cudaGetSymbolAddress((void**)&pWH,  g_WtH);
    cudaGetSymbolAddress((void**)&pWL,  g_WtL);

    cudaFuncSetAttribute(gemm_bf16s, cudaFuncAttributeMaxDynamicSharedMemorySize,
                         GEMM_SMEM);
    cudaFuncSetAttribute(proj_mma, cudaFuncAttributeMaxDynamicSharedMemorySize,
                         PROJ_SMEM);

    const int n4 = MROWS * HIDDEN / 4;
    const long WOFF = (long)HIDDEN * KHALF;

    // prep: activation split, weight transpose+split, E^T
    split_pack<<<(n4 + 255) / 256, 256>>>(hs, pAH, pAL, n4);
    dim3 tgrid(HIDDEN / 32, HIDDEN / 32, 4);          // (24,24,4)
    wsplit4<<<tgrid, 256>>>(Wq, Wk, Wv, Wo, pWH, pWL);
    const int etN = 2 * KRANK * KPAD;
    et_prep<<<(etN + 255) / 256, 256>>>(Ek, Ev, pEt);

    // fused QKV projections (split-bf16 HMMA)
    GSet sq = { pWH + 0 * WOFF, pWL + 0 * WOFF, bq, pQ };
    GSet sk = { pWH + 1 * WOFF, pWL + 1 * WOFF, bk, pK };
    GSet sv = { pWH + 2 * WOFF, pWL + 2 * WOFF, bv, pV };
    dim3 ggrid3(HIDDEN / 128, (MROWS + 127) / 128, 3);   // (6, 99, 3)
    gemm_bf16s<<<ggrid3, 256, GEMM_SMEM>>>(pAH, pAL, sq, sk, sv);

    // low-rank projections (tf32)
    dim3 pgrid(HIDDEN / 128, BATCH, 2);                  // (6, 64, 2)
    proj_mma<<<pgrid, 256, PROJ_SMEM>>>(pEt, pK, pV, pPK, pPV);

    // attention (fp32)
    dim3 attnGrid(HEADS, BATCH);
    lowrank_attn<<<attnGrid, 128>>>(pQ, pPK, pPV, pCTX);

    // output projection
    split_pack<<<(n4 + 255) / 256, 256>>>(pCTX, pAH, pAL, n4);
    GSet so = { pWH + 3 * WOFF, pWL + 3 * WOFF, bo, out };
    dim3 ggrid1(HIDDEN / 128, (MROWS + 127) / 128, 1);
    gemm_bf16s<<<ggrid1, 256, GEMM_SMEM>>>(pAH, pAL, so, so, so);
}

// round 14
// speedup vs baseline: 1.6144x; 1.3472x over previous
#include <cuda_runtime.h>
#include <cuda_bf16.h>
#include <cstdint>
#include <math.h>

// Problem constants
#define BATCH   64
#define SEQ     197
#define HIDDEN  768
#define HEADS   12
#define HDIM    64
#define KRANK   64
#define MROWS   (BATCH * SEQ)          // 12608
#define HH      (HIDDEN * HIDDEN)
#define KPAD    224                    // SEQ padded to 7*32

// ---------------------------------------------------------------------------
// Scratch (no allocations allowed): device globals
// ---------------------------------------------------------------------------
__device__ float g_Q  [MROWS * HIDDEN];
__device__ float g_K  [MROWS * HIDDEN];
__device__ float g_V  [MROWS * HIDDEN];
__device__ float g_CTX[MROWS * HIDDEN];
__device__ float g_PK [BATCH * KRANK * HIDDEN];
__device__ float g_PV [BATCH * KRANK * HIDDEN];
__device__ float g_Wt [4 * HH];            // transposed + rounded + col-permuted weights
__device__ float g_Et [2 * KRANK * KPAD];  // E^T, tf32-rounded, zero-padded

// ---------------------------------------------------------------------------
// Helpers
// ---------------------------------------------------------------------------
static __device__ __forceinline__ uint32_t smem_u32(const void* p) {
    uint32_t a;
    asm("{ .reg .u64 t; cvta.to.shared.u64 t, %1; cvt.u32.u64 %0, t; }"
        : "=r"(a) : "l"(p));
    return a;
}
static __device__ __forceinline__ void cpa16(uint32_t s, const void* g) {
    asm volatile("cp.async.cg.shared.global [%0], [%1], 16;" :: "r"(s), "l"(g));
}
static __device__ __forceinline__ float rna_tf32(float x) {
    uint32_t u;
    asm("cvt.rna.tf32.f32 %0, %1;" : "=r"(u) : "f"(x));
    return __uint_as_float(u);
}
static __device__ __forceinline__ uint32_t rna_u(float x) {
    uint32_t u;
    asm("cvt.rna.tf32.f32 %0, %1;" : "=r"(u) : "f"(x));
    return u;
}
static __device__ __forceinline__ void mma_tf32(
    float* c, const uint32_t* a, uint32_t b0, uint32_t b1)
{
    asm volatile(
        "mma.sync.aligned.m16n8k8.row.col.f32.tf32.tf32.f32 "
        "{%0,%1,%2,%3}, {%4,%5,%6,%7}, {%8,%9}, {%0,%1,%2,%3};"
        : "+f"(c[0]), "+f"(c[1]), "+f"(c[2]), "+f"(c[3])
        : "r"(a[0]), "r"(a[1]), "r"(a[2]), "r"(a[3]), "r"(b0), "r"(b1));
}

struct GSet { const float* Bt; const float* bias; float* C; };

// ---------------------------------------------------------------------------
// tf32 HMMA GEMM: C[M,768] = A[M,768] @ W + bias
//   W transposed [n][k], tf32-rounded, k-cols permuted per 32-block:
//   p(c) = (c&3)*8 + (c>>2)  -> per-thread B fragments become float4 loads.
//   A raw fp32, rounded per-fragment in registers.
// CTA tile 128x128, 8 warps (2x4, warp tile 64x32), K-chunk 32,
// 2-stage cp.async pipeline (73.7KB smem), 2 CTAs/SM for latency hiding
// (R13 evidence: 1-CTA version is latency-bound at tensor=37-50%).
// ---------------------------------------------------------------------------
#define LDP 36
#define STAGE_F (2 * 128 * LDP)          // 9216 floats
#define GEMM_SMEM (2 * STAGE_F * 4)      // 73728 bytes -> 2 CTAs/SM

__global__ __launch_bounds__(256, 2) void gemm_tf32(
    const float* __restrict__ A, GSet s0, GSet s1, GSet s2)
{
    extern __shared__ float sm[];
    const GSet g = (blockIdx.z == 0) ? s0 : (blockIdx.z == 1) ? s1 : s2;
    const float* __restrict__ Bt   = g.Bt;
    const float* __restrict__ bias = g.bias;
    float* __restrict__ C          = g.C;

    const int tid  = threadIdx.x;
    const int wid  = tid >> 5;
    const int lane = tid & 31;
    const int gid  = lane >> 2;
    const int tg   = lane & 3;
    const int wm   = (wid >> 2) * 64;
    const int wn   = (wid & 3) * 32;
    const int row0 = blockIdx.y * 128;
    const int col0 = blockIdx.x * 128;

    const int lrow = tid >> 3;
    const int lseg = tid & 7;

    float acc[4][4][4];
    #pragma unroll
    for (int i = 0; i < 4; ++i)
        #pragma unroll
        for (int j = 0; j < 4; ++j)
            #pragma unroll
            for (int r = 0; r < 4; ++r) acc[i][j][r] = 0.f;

#define LOAD_STAGE(s, t) do {                                                  \
    const int _k0 = (t) * 32;                                                  \
    float* _dA = sm + (s) * STAGE_F;                                           \
    float* _dB = _dA + 128 * LDP;                                              \
    _Pragma("unroll")                                                          \
    for (int _i = 0; _i < 4; ++_i) {                                           \
        int _row = lrow + _i * 32;                                             \
        int _ar = row0 + _row; if (_ar > MROWS - 1) _ar = MROWS - 1;           \
        cpa16(smem_u32(_dA + _row * LDP + lseg * 4),                           \
              A + (long)_ar * HIDDEN + _k0 + lseg * 4);                        \
        cpa16(smem_u32(_dB + _row * LDP + lseg * 4),                           \
              Bt + (long)(col0 + _row) * HIDDEN + _k0 + lseg * 4);             \
    }                                                                          \
    asm volatile("cp.async.commit_group;" ::: "memory");                       \
} while (0)

    LOAD_STAGE(0, 0);
    LOAD_STAGE(1, 1);

    for (int t = 0; t < 24; ++t) {
        if (t < 23) asm volatile("cp.async.wait_group 1;" ::: "memory");
        else        asm volatile("cp.async.wait_group 0;" ::: "memory");
        __syncthreads();              // stage t data visible to all warps

        const float* As = sm + (t & 1) * STAGE_F;
        const float* Bs = As + 128 * LDP;

        uint32_t a[4][4];
        float4 bv[4];

        #pragma unroll
        for (int k8 = 0; k8 < 4; ++k8) {
            const int kb = k8 * 8;
            if ((k8 & 1) == 0) {
                // permuted layout: one float4 covers this k8-pair's B frags
                #pragma unroll
                for (int nj = 0; nj < 4; ++nj) {
                    const int n = wn + nj * 8 + gid;
                    bv[nj] = *(const float4*)&Bs[n * LDP + tg * 8 + (k8 >> 1) * 4];
                }
            }
            #pragma unroll
            for (int mi = 0; mi < 4; ++mi) {
                const int r = wm + mi * 16 + gid;
                a[mi][0] = rna_u(As[r       * LDP + kb + tg]);
                a[mi][1] = rna_u(As[(r + 8) * LDP + kb + tg]);
                a[mi][2] = rna_u(As[r       * LDP + kb + tg + 4]);
                a[mi][3] = rna_u(As[(r + 8) * LDP + kb + tg + 4]);
            }
            #pragma unroll
            for (int mi = 0; mi < 4; ++mi)
                #pragma unroll
                for (int nj = 0; nj < 4; ++nj) {
                    const uint32_t b0 = (k8 & 1) ? __float_as_uint(bv[nj].z)
                                                 : __float_as_uint(bv[nj].x);
                    const uint32_t b1 = (k8 & 1) ? __float_as_uint(bv[nj].w)
                                                 : __float_as_uint(bv[nj].y);
                    mma_tf32(acc[mi][nj], a[mi], b0, b1);
                }
        }
        __syncthreads();              // all warps done with stage t
        if (t + 2 < 24) LOAD_STAGE(t & 1, t + 2);   // overwrite freed buffer
    }
#undef LOAD_STAGE

    // epilogue
    #pragma unroll
    for (int nj = 0; nj < 4; ++nj) {
        const int cb = col0 + wn + nj * 8 + tg * 2;
        const float bx = bias[cb];
        const float by = bias[cb + 1];
        #pragma unroll
        for (int mi = 0; mi < 4; ++mi) {
            const int r = row0 + wm + mi * 16 + gid;
            if (r < MROWS) {
                float2 v = make_float2(acc[mi][nj][0] + bx, acc[mi][nj][1] + by);
                *(float2*)(C + (long)r * HIDDEN + cb) = v;
            }
            if (r + 8 < MROWS) {
                float2 v = make_float2(acc[mi][nj][2] + bx, acc[mi][nj][3] + by);
                *(float2*)(C + (long)(r + 8) * HIDDEN + cb) = v;
            }
        }
    }
}

// ---------------------------------------------------------------------------
// Low-rank projection on tensor cores:
//   OUT[b][k][c] = sum_s Et[k][s] * SRC[b*SEQ+s][c],  K-dim padded to 224
// CTA tile 64x128, 8 warps (2x4, warp tile 32x32), grid (6, BATCH, 2).
// ---------------------------------------------------------------------------
#define PLDB 132
#define PSTAGE_F (64 * LDP + 32 * PLDB)     // 6528 floats
#define PROJ_SMEM (3 * PSTAGE_F * 4)        // 78336 bytes

__global__ __launch_bounds__(256, 2) void proj_mma(
    const float* __restrict__ Et2,   // [2][KRANK][KPAD]
    const float* __restrict__ K_,
    const float* __restrict__ V_,
    float* __restrict__ PK_, float* __restrict__ PV_)
{
    extern __shared__ float smf[];
    const int zsel = blockIdx.z;
    const float* __restrict__ Et  = Et2 + (long)zsel * KRANK * KPAD;
    const float* __restrict__ SRC = zsel ? V_ : K_;
    float* __restrict__ OUT       = zsel ? PV_ : PK_;

    const int tid  = threadIdx.x;
    const int wid  = tid >> 5;
    const int lane = tid & 31;
    const int gid  = lane >> 2;
    const int tg   = lane & 3;
    const int wm   = (wid >> 2) * 32;
    const int wn   = (wid & 3) * 32;
    const int col0 = blockIdx.x * 128;
    const int b    = blockIdx.y;

    float acc[2][4][4];
    #pragma unroll
    for (int i = 0; i < 2; ++i)
        #pragma unroll
        for (int j = 0; j < 4; ++j)
            #pragma unroll
            for (int r = 0; r < 4; ++r) acc[i][j][r] = 0.f;

#define PLOAD_STAGE(s, t) do {                                                 \
    const int _k0 = (t) * 32;                                                  \
    float* _dA = smf + (s) * PSTAGE_F;                                         \
    float* _dB = _dA + 64 * LDP;                                               \
    _Pragma("unroll")                                                          \
    for (int _i = 0; _i < 2; ++_i) {                                           \
        int _idx = _i * 256 + tid;                                             \
        int _row = _idx >> 3, _seg = _idx & 7;                                 \
        cpa16(smem_u32(_dA + _row * LDP + _seg * 4),                           \
              Et + (long)_row * KPAD + _k0 + _seg * 4);                        \
    }                                                                          \
    _Pragma("unroll")                                                          \
    for (int _i = 0; _i < 4; ++_i) {                                           \
        int _idx = _i * 256 + tid;                                             \
        int _row = _idx >> 5, _seg = _idx & 31;                                \
        int _s = _k0 + _row; if (_s > SEQ - 1) _s = SEQ - 1;                   \
        cpa16(smem_u32(_dB + _row * PLDB + _seg * 4),                          \
              SRC + ((long)b * SEQ + _s) * HIDDEN + col0 + _seg * 4);          \
    }                                                                          \
    asm volatile("cp.async.commit_group;" ::: "memory");                       \
} while (0)

    PLOAD_STAGE(0, 0);
    PLOAD_STAGE(1, 1);

    for (int t = 0; t < 7; ++t) {
        if (t < 6) asm volatile("cp.async.wait_group 1;" ::: "memory");
        else       asm volatile("cp.async.wait_group 0;" ::: "memory");
        __syncthreads();

        if (t < 5) PLOAD_STAGE((t + 2) % 3, t + 2);

        const float* As = smf + (t % 3) * PSTAGE_F;
        const float* Bs = As + 64 * LDP;

        #pragma unroll
        for (int k8 = 0; k8 < 4; ++k8) {
            const int kb = k8 * 8;
            uint32_t a[2][4], bb[4][2];
            #pragma unroll
            for (int mi = 0; mi < 2; ++mi) {
                const int r = wm + mi * 16 + gid;
                a[mi][0] = __float_as_uint(As[r       * LDP + kb + tg]);
                a[mi][1] = __float_as_uint(As[(r + 8) * LDP + kb + tg]);
                a[mi][2] = __float_as_uint(As[r       * LDP + kb + tg + 4]);
                a[mi][3] = __float_as_uint(As[(r + 8) * LDP + kb + tg + 4]);
            }
            #pragma unroll
            for (int nj = 0; nj < 4; ++nj) {
                const int n = wn + nj * 8 + gid;
                bb[nj][0] = rna_u(Bs[(kb + tg)     * PLDB + n]);
                bb[nj][1] = rna_u(Bs[(kb + tg + 4) * PLDB + n]);
            }
            #pragma unroll
            for (int mi = 0; mi < 2; ++mi)
                #pragma unroll
                for (int nj = 0; nj < 4; ++nj)
                    mma_tf32(acc[mi][nj], a[mi], bb[nj][0], bb[nj][1]);
        }
    }
#undef PLOAD_STAGE

    #pragma unroll
    for (int nj = 0; nj < 4; ++nj) {
        const int cb = col0 + wn + nj * 8 + tg * 2;
        #pragma unroll
        for (int mi = 0; mi < 2; ++mi) {
            const int r = wm + mi * 16 + gid;
            float2 v0 = make_float2(acc[mi][nj][0], acc[mi][nj][1]);
            float2 v1 = make_float2(acc[mi][nj][2], acc[mi][nj][3]);
            *(float2*)(OUT + ((long)b * KRANK + r)     * HIDDEN + cb) = v0;
            *(float2*)(OUT + ((long)b * KRANK + r + 8) * HIDDEN + cb) = v1;
        }
    }
}

// ---------------------------------------------------------------------------
// Weight transpose + tf32 round + per-32-block column permutation:
//   T[n][kblk + p(klocal)] = rna(W[k][n]),  p(c) = (c&3)*8 + (c>>2)
// ---------------------------------------------------------------------------
__global__ __launch_bounds__(256) void wtrans_round4(
    const float* __restrict__ W0, const float* __restrict__ W1,
    const float* __restrict__ W2, const float* __restrict__ W3,
    float* __restrict__ Tbase)
{
    const float* W = (blockIdx.z == 0) ? W0 : (blockIdx.z == 1) ? W1
                   : (blockIdx.z == 2) ? W2 : W3;
    float* T = Tbase + (long)blockIdx.z * HH;

    __shared__ float t[32][33];
    const int bx = blockIdx.x * 32;   // n
    const int by = blockIdx.y * 32;   // k block (32-aligned)
    const int x = threadIdx.x & 31, y = threadIdx.x >> 5;
    #pragma unroll
    for (int i = 0; i < 32; i += 8)
        t[y + i][x] = W[(by + y + i) * HIDDEN + bx + x];
    __syncthreads();
    const int p = (x & 3) * 8 + (x >> 2);   // permuted k position within block
    #pragma unroll
    for (int i = 0; i < 32; i += 8)
        T[(bx + y + i) * HIDDEN + by + p] = rna_tf32(t[x][y + i]);
}

// ---------------------------------------------------------------------------
// E^T prep: Et[z][m][s] = rna(E_z[s][m]) for s<197 else 0
// ---------------------------------------------------------------------------
__global__ __launch_bounds__(256) void et_prep(
    const float* __restrict__ Ek, const float* __restrict__ Ev,
    float* __restrict__ Et2)
{
    int idx = blockIdx.x * 256 + threadIdx.x;
    if (idx >= 2 * KRANK * KPAD) return;
    int z = idx / (KRANK * KPAD);
    int r = idx % (KRANK * KPAD);
    int m = r / KPAD, s = r % KPAD;
    const float* E = z ? Ev : Ek;
    Et2[idx] = (s < SEQ) ? rna_tf32(E[s * KRANK + m]) : 0.f;
}

// ---------------------------------------------------------------------------
// Fused low-rank attention per (b,h) (fp32)
// ---------------------------------------------------------------------------
__global__ __launch_bounds__(128) void lowrank_attn(
    const float* __restrict__ Q, const float* __restrict__ PK,
    const float* __restrict__ PV, float* __restrict__ CTX)
{
    const int h = blockIdx.x;
    const int b = blockIdx.y;

    __shared__ float pk_s[64 * 65];
    __shared__ float pv_s[64 * 64];
    __shared__ float qs[4][64];
    __shared__ float ps[4][64];

    const int tid  = threadIdx.x;
    const int w    = tid >> 5;
    const int lane = tid & 31;

    const float* pkg = PK + ((long)b * KRANK) * HIDDEN + h * HDIM;
    const float* pvg = PV + ((long)b * KRANK) * HIDDEN + h * HDIM;
    for (int i = tid; i < 64 * 64; i += 128) {
        int k = i >> 6, d = i & 63;
        pk_s[k * 65 + d] = pkg[(long)k * HIDDEN + d];
        pv_s[k * 64 + d] = pvg[(long)k * HIDDEN + d];
    }
    __syncthreads();

    const float scale = 0.125f;

    for (int s = w; s < SEQ; s += 4) {
        const float* qg = Q + ((long)b * SEQ + s) * HIDDEN + h * HDIM;
        qs[w][lane]      = qg[lane];
        qs[w][lane + 32] = qg[lane + 32];
        __syncwarp();

        float s0 = 0.f, s1 = 0.f;
        const float* p0 = &pk_s[lane * 65];
        const float* p1 = &pk_s[(lane + 32) * 65];
        #pragma unroll
        for (int d = 0; d < 64; ++d) {
            float qd = qs[w][d];
            s0 = fmaf(qd, p0[d], s0);
            s1 = fmaf(qd, p1[d], s1);
        }
        s0 *= scale; s1 *= scale;

        float mx = fmaxf(s0, s1);
        #pragma unroll
        for (int o = 16; o > 0; o >>= 1)
            mx = fmaxf(mx, __shfl_xor_sync(0xffffffffu, mx, o));
        float e0 = expf(s0 - mx);
        float e1 = expf(s1 - mx);
        float sm = e0 + e1;
        #pragma unroll
        for (int o = 16; o > 0; o >>= 1)
            sm += __shfl_xor_sync(0xffffffffu, sm, o);
        float inv = 1.f / sm;
        ps[w][lane]      = e0 * inv;
        ps[w][lane + 32] = e1 * inv;
        __syncwarp();

        float c0 = 0.f, c1 = 0.f;
        #pragma unroll
        for (int k = 0; k < 64; ++k) {
            float p = ps[w][k];
            c0 = fmaf(p, pv_s[k * 64 + lane],      c0);
            c1 = fmaf(p, pv_s[k * 64 + lane + 32], c1);
        }
        float* cg = CTX + ((long)b * SEQ + s) * HIDDEN + h * HDIM;
        cg[lane]      = c0;
        cg[lane + 32] = c1;
        __syncwarp();
    }
}

// ---------------------------------------------------------------------------
// Launch orchestration
// ---------------------------------------------------------------------------
extern "C" void kernel_launch(void* const* d_in, const int* in_sizes, int n_in,
                              void* d_out, int out_size)
{
    const float* hs = (const float*)d_in[0];
    const float* Wq = (const float*)d_in[1];
    const float* bq = (const float*)d_in[2];
    const float* Wk = (const float*)d_in[3];
    const float* bk = (const float*)d_in[4];
    const float* Wv = (const float*)d_in[5];
    const float* bv = (const float*)d_in[6];
    const float* Wo = (const float*)d_in[7];
    const float* bo = (const float*)d_in[8];
    const float* Ek = (const float*)d_in[9];
    const float* Ev = (const float*)d_in[10];
    float* out = (float*)d_out;

    float *pQ, *pK, *pV, *pCTX, *pPK, *pPV, *pWt, *pEt;
    cudaGetSymbolAddress((void**)&pQ,   g_Q);
    cudaGetSymbolAddress((void**)&pK,   g_K);
    cudaGetSymbolAddress((void**)&pV,   g_V);
    cudaGetSymbolAddress((void**)&pCTX, g_CTX);
    cudaGetSymbolAddress((void**)&pPK,  g_PK);
    cudaGetSymbolAddress((void**)&pPV,  g_PV);
    cudaGetSymbolAddress((void**)&pWt,  g_Wt);
    cudaGetSymbolAddress((void**)&pEt,  g_Et);

    cudaFuncSetAttribute(gemm_tf32, cudaFuncAttributeMaxDynamicSharedMemorySize,
                         GEMM_SMEM);
    cudaFuncSetAttribute(proj_mma, cudaFuncAttributeMaxDynamicSharedMemorySize,
                         PROJ_SMEM);

    // prep
    dim3 tgrid(HIDDEN / 32, HIDDEN / 32, 4);          // (24,24,4)
    wtrans_round4<<<tgrid, 256>>>(Wq, Wk, Wv, Wo, pWt);
    const int etN = 2 * KRANK * KPAD;
    et_prep<<<(etN + 255) / 256, 256>>>(Ek, Ev, pEt);

    // fused QKV projections
    GSet sq = { pWt + 0 * HH, bq, pQ };
    GSet sk = { pWt + 1 * HH, bk, pK };
    GSet sv = { pWt + 2 * HH, bv, pV };
    dim3 ggrid3(HIDDEN / 128, (MROWS + 127) / 128, 3);   // (6, 99, 3)
    gemm_tf32<<<ggrid3, 256, GEMM_SMEM>>>(hs, sq, sk, sv);

    // low-rank projections
    dim3 pgrid(HIDDEN / 128, BATCH, 2);                  // (6, 64, 2)
    proj_mma<<<pgrid, 256, PROJ_SMEM>>>(pEt, pK, pV, pPK, pPV);

    // attention
    dim3 attnGrid(HEADS, BATCH);
    lowrank_attn<<<attnGrid, 128>>>(pQ, pPK, pPV, pCTX);

    // output projection
    GSet so = { pWt + 3 * HH, bo, out };
    dim3 ggrid1(HIDDEN / 128, (MROWS + 127) / 128, 1);   // (6, 99, 1)
    gemm_tf32<<<ggrid1, 256, GEMM_SMEM>>>(pCTX, so, so, so);
}